// round 2
// baseline (speedup 1.0000x reference)
#include <cuda_runtime.h>
#include <math.h>

// Problem constants
#define Bb 2
#define LL 2048
#define EE 512
#define HH 8
#define DD 64
#define MTOT (Bb*LL)      // 4096 rows
#define NWORDS (LL/32)    // 64 mask words per row

// Scratch (device globals -- no allocation allowed)
__device__ float g_q[Bb*HH*LL*DD];
__device__ float g_k[Bb*HH*LL*DD];
__device__ float g_v[Bb*HH*LL*DD];
__device__ float g_o[Bb*LL*EE];
__device__ unsigned int g_mb[Bb*LL*NWORDS];

// ---------------------------------------------------------------------------
// Pack mask [B,1,L,L] int32 -> bitmask words
// ---------------------------------------------------------------------------
__global__ void pack_mask_kernel(const int* __restrict__ mask) {
    int idx = blockIdx.x * blockDim.x + threadIdx.x;
    if (idx >= Bb*LL*NWORDS) return;
    const int* p = mask + (size_t)idx * 32;
    unsigned int bits = 0u;
    #pragma unroll
    for (int i = 0; i < 32; i++) bits |= (p[i] != 0 ? 1u : 0u) << i;
    g_mb[idx] = bits;
}

// ---------------------------------------------------------------------------
// GEMM: C[M,N] = A[M,K] @ W^T + bias   (W is [N,K] row-major, torch Linear)
// M=4096, N=512, K=512 fixed. outsel: 0->g_v 1->g_k 2->g_q (head-split
// [B,H,L,D] layout), 3->C plain row-major. A==nullptr means read from g_o.
// ---------------------------------------------------------------------------
#define GM 4096
#define GN 512
#define GK 512
#define BM 64
#define BN 64
#define BKT 16

__global__ __launch_bounds__(256) void gemm_bias_kernel(
    const float* __restrict__ A, const float* __restrict__ W,
    const float* __restrict__ bias, float* __restrict__ C, int outsel)
{
    __shared__ float As[BKT][BM];
    __shared__ float Ws[BKT][BN];

    const float* Ap = (A == nullptr) ? g_o : A;
    float* Cp;
    if      (outsel == 0) Cp = g_v;
    else if (outsel == 1) Cp = g_k;
    else if (outsel == 2) Cp = g_q;
    else                  Cp = C;

    int tid = threadIdx.x;
    int tx = tid % 16;          // col group
    int ty = tid / 16;          // row group
    int m0 = blockIdx.y * BM;
    int n0 = blockIdx.x * BN;

    int lr = tid / 4;           // 0..63 row within tile
    int lk = (tid % 4) * 4;     // k offset within BKT

    float acc[4][4];
    #pragma unroll
    for (int i = 0; i < 4; i++)
        #pragma unroll
        for (int j = 0; j < 4; j++) acc[i][j] = 0.f;

    for (int k0 = 0; k0 < GK; k0 += BKT) {
        float4 av = *(const float4*)&Ap[(size_t)(m0 + lr) * GK + k0 + lk];
        float4 wv = *(const float4*)&W [(size_t)(n0 + lr) * GK + k0 + lk];
        As[lk+0][lr] = av.x; As[lk+1][lr] = av.y; As[lk+2][lr] = av.z; As[lk+3][lr] = av.w;
        Ws[lk+0][lr] = wv.x; Ws[lk+1][lr] = wv.y; Ws[lk+2][lr] = wv.z; Ws[lk+3][lr] = wv.w;
        __syncthreads();

        #pragma unroll
        for (int kk = 0; kk < BKT; kk++) {
            float4 a4 = *(const float4*)&As[kk][ty * 4];
            float4 w4 = *(const float4*)&Ws[kk][tx * 4];
            float a[4] = {a4.x, a4.y, a4.z, a4.w};
            float w[4] = {w4.x, w4.y, w4.z, w4.w};
            #pragma unroll
            for (int i = 0; i < 4; i++)
                #pragma unroll
                for (int j = 0; j < 4; j++)
                    acc[i][j] = fmaf(a[i], w[j], acc[i][j]);
        }
        __syncthreads();
    }

    #pragma unroll
    for (int i = 0; i < 4; i++) {
        int m = m0 + ty * 4 + i;
        #pragma unroll
        for (int j = 0; j < 4; j++) {
            int n = n0 + tx * 4 + j;
            float val = acc[i][j] + bias[n];
            if (outsel < 3) {
                int b = m / LL, l = m % LL;
                int h = n / DD, d = n % DD;
                Cp[(((size_t)(b * HH + h)) * LL + l) * DD + d] = val;
            } else {
                Cp[(size_t)m * GN + n] = val;
            }
        }
    }
}

// ---------------------------------------------------------------------------
// Fused flash attention: per (b,h), Q tile of 128 rows per CTA, K/V tiles of
// 64 rows in SMEM. Online softmax in two 32-wide halves (register pressure).
// Writes O as [B, L, E] (= [B, L, H, D]) ready for the output projection.
// ---------------------------------------------------------------------------
#define BQ 128
#define BKK 64
#define SCALE 0.04419417382415922f          // 1/sqrt(512)
#define MASKVAL (-4.4194173824159216e18f)   // -1e20 * SCALE

__global__ __launch_bounds__(128) void attn_kernel()
{
    __shared__ float Ks[BKK][DD];
    __shared__ float Vs[BKK][DD];

    int r  = threadIdx.x;                // one query row per thread
    int bh = blockIdx.y;
    int b  = bh / HH;
    int h  = bh % HH;
    int qi = blockIdx.x * BQ + r;

    const float* qptr = g_q + ((size_t)bh * LL + qi) * DD;
    float4 q[16];
    #pragma unroll
    for (int i = 0; i < 16; i++) q[i] = *(const float4*)&qptr[i * 4];

    float4 o[16];
    #pragma unroll
    for (int i = 0; i < 16; i++) o[i] = make_float4(0.f, 0.f, 0.f, 0.f);

    float m = -1e30f, l = 0.f;

    const unsigned int* mrow = g_mb + ((size_t)b * LL + qi) * NWORDS;

    for (int k0 = 0; k0 < LL; k0 += BKK) {
        // cooperative K/V tile load (1024 float4 each, 128 threads -> 8 iters)
        const float4* kbase = (const float4*)(g_k + ((size_t)bh * LL + k0) * DD);
        const float4* vbase = (const float4*)(g_v + ((size_t)bh * LL + k0) * DD);
        float4* ksh = (float4*)Ks;
        float4* vsh = (float4*)Vs;
        #pragma unroll
        for (int i = 0; i < 8; i++) {
            ksh[r + i * 128] = kbase[r + i * 128];
            vsh[r + i * 128] = vbase[r + i * 128];
        }
        __syncthreads();

        unsigned int wb0 = mrow[(k0 >> 5) + 0];
        unsigned int wb1 = mrow[(k0 >> 5) + 1];

        #pragma unroll
        for (int half = 0; half < 2; half++) {
            unsigned int bits = half ? wb1 : wb0;
            float s[32];
            float tmax = -3.0e38f;
            #pragma unroll
            for (int kk = 0; kk < 32; kk++) {
                const float4* kr = (const float4*)&Ks[half * 32 + kk][0];
                float4 a4 = make_float4(0.f, 0.f, 0.f, 0.f);
                #pragma unroll
                for (int i = 0; i < 16; i++) {
                    float4 kv = kr[i];
                    a4.x = fmaf(q[i].x, kv.x, a4.x);
                    a4.y = fmaf(q[i].y, kv.y, a4.y);
                    a4.z = fmaf(q[i].z, kv.z, a4.z);
                    a4.w = fmaf(q[i].w, kv.w, a4.w);
                }
                float acc = (a4.x + a4.y) + (a4.z + a4.w);
                float sv = ((bits >> kk) & 1u) ? acc * SCALE : MASKVAL;
                s[kk] = sv;
                tmax = fmaxf(tmax, sv);
            }
            float mnew = fmaxf(m, tmax);
            float corr = __expf(m - mnew);
            l *= corr;
            #pragma unroll
            for (int i = 0; i < 16; i++) {
                o[i].x *= corr; o[i].y *= corr; o[i].z *= corr; o[i].w *= corr;
            }
            #pragma unroll
            for (int kk = 0; kk < 32; kk++) {
                float p = __expf(s[kk] - mnew);
                l += p;
                const float4* vr = (const float4*)&Vs[half * 32 + kk][0];
                #pragma unroll
                for (int i = 0; i < 16; i++) {
                    float4 vv = vr[i];
                    o[i].x = fmaf(p, vv.x, o[i].x);
                    o[i].y = fmaf(p, vv.y, o[i].y);
                    o[i].z = fmaf(p, vv.z, o[i].z);
                    o[i].w = fmaf(p, vv.w, o[i].w);
                }
            }
            m = mnew;
        }
        __syncthreads();
    }

    float inv = 1.f / l;
    float* optr = g_o + ((size_t)(b * LL + qi)) * EE + h * DD;
    #pragma unroll
    for (int i = 0; i < 16; i++) {
        float4 ov = make_float4(o[i].x * inv, o[i].y * inv, o[i].z * inv, o[i].w * inv);
        *(float4*)&optr[i * 4] = ov;
    }
}

// ---------------------------------------------------------------------------
// kernel_launch
// inputs: 0 values, 1 keys, 2 query, 3 mask, 4 Wv, 5 bv, 6 Wk, 7 bk,
//         8 Wq, 9 bq, 10 Wo, 11 bo
// ---------------------------------------------------------------------------
extern "C" void kernel_launch(void* const* d_in, const int* in_sizes, int n_in,
                              void* d_out, int out_size)
{
    const float* values = (const float*)d_in[0];
    const float* keys   = (const float*)d_in[1];
    const float* query  = (const float*)d_in[2];
    const int*   mask   = (const int*)d_in[3];
    const float* Wv = (const float*)d_in[4];
    const float* bv = (const float*)d_in[5];
    const float* Wk = (const float*)d_in[6];
    const float* bk = (const float*)d_in[7];
    const float* Wq = (const float*)d_in[8];
    const float* bq = (const float*)d_in[9];
    const float* Wo = (const float*)d_in[10];
    const float* bo = (const float*)d_in[11];
    float* out = (float*)d_out;

    // mask bit-pack
    pack_mask_kernel<<<(Bb*LL*NWORDS + 255) / 256, 256>>>(mask);

    // projections (head-split outputs)
    dim3 ggrid(GN / BN, GM / BM);   // (8, 64)
    gemm_bias_kernel<<<ggrid, 256>>>(values, Wv, bv, nullptr, 0);  // -> g_v
    gemm_bias_kernel<<<ggrid, 256>>>(keys,   Wk, bk, nullptr, 1);  // -> g_k
    gemm_bias_kernel<<<ggrid, 256>>>(query,  Wq, bq, nullptr, 2);  // -> g_q

    // fused attention -> g_o [B, L, E]
    attn_kernel<<<dim3(LL / BQ, Bb * HH), 128>>>();

    // output projection -> d_out
    gemm_bias_kernel<<<ggrid, 256>>>(nullptr, Wo, bo, out, 3);     // g_o @ Wo^T + bo
}

// round 3
// speedup vs baseline: 1.5852x; 1.5852x over previous
#include <cuda_runtime.h>
#include <math.h>

// Problem constants
#define Bb 2
#define LL 2048
#define EE 512
#define HH 8
#define DD 64
#define NWORDS (LL/32)    // 64 mask words per row

// Scratch (device globals -- no allocation allowed)
__device__ float g_q[Bb*HH*LL*DD];
__device__ float g_k[Bb*HH*LL*DD];
__device__ float g_v[Bb*HH*LL*DD];
__device__ float g_o[Bb*LL*EE];
__device__ unsigned int g_mb[Bb*LL*NWORDS];

// ---------------------------------------------------------------------------
// Packed fp32x2 helpers (Blackwell sm_103a packed-FMA pipe)
// ---------------------------------------------------------------------------
typedef unsigned long long u64;

__device__ __forceinline__ u64 pack2(float lo, float hi) {
    u64 r; asm("mov.b64 %0, {%1, %2};" : "=l"(r) : "f"(lo), "f"(hi)); return r;
}
__device__ __forceinline__ void unpack2(u64 v, float &lo, float &hi) {
    asm("mov.b64 {%0, %1}, %2;" : "=f"(lo), "=f"(hi) : "l"(v));
}
__device__ __forceinline__ u64 ffma2(u64 a, u64 b, u64 c) {
    u64 d; asm("fma.rn.f32x2 %0, %1, %2, %3;" : "=l"(d) : "l"(a), "l"(b), "l"(c)); return d;
}
__device__ __forceinline__ u64 fadd2(u64 a, u64 b) {
    u64 d; asm("add.rn.f32x2 %0, %1, %2;" : "=l"(d) : "l"(a), "l"(b)); return d;
}
__device__ __forceinline__ u64 fmul2(u64 a, u64 b) {
    u64 d; asm("mul.rn.f32x2 %0, %1, %2;" : "=l"(d) : "l"(a), "l"(b)); return d;
}

// ---------------------------------------------------------------------------
// Pack mask [B,1,L,L] int32 -> bitmask words via warp ballot (coalesced)
// ---------------------------------------------------------------------------
__global__ void pack_mask_kernel(const int* __restrict__ mask) {
    int idx = blockIdx.x * blockDim.x + threadIdx.x;   // over Bb*LL*LL elements
    unsigned int bit = (mask[idx] != 0) ? 1u : 0u;
    unsigned int word = __ballot_sync(0xffffffffu, bit);
    if ((threadIdx.x & 31) == 0) g_mb[idx >> 5] = word;
}

// ---------------------------------------------------------------------------
// GEMM: C[M,N] = A[M,K] @ W^T + bias   (W is [N,K] row-major, torch Linear)
// M=4096, N=512, K=512. outsel: 0->g_v 1->g_k 2->g_q (head-split [B,H,L,D]),
// 3->C plain row-major. A==nullptr means read from g_o.
// Microkernel uses packed fp32x2 FMA: accumulators packed along the row dim
// so the A operand comes pre-packed from a single LDS.128.
// ---------------------------------------------------------------------------
#define GM 4096
#define GN 512
#define GK 512
#define BM 64
#define BN 64
#define BKT 16

__global__ __launch_bounds__(256) void gemm_bias_kernel(
    const float* __restrict__ A, const float* __restrict__ W,
    const float* __restrict__ bias, float* __restrict__ C, int outsel)
{
    __shared__ float As[BKT][BM];
    __shared__ float Ws[BKT][BN];

    const float* Ap = (A == nullptr) ? g_o : A;
    float* Cp;
    if      (outsel == 0) Cp = g_v;
    else if (outsel == 1) Cp = g_k;
    else if (outsel == 2) Cp = g_q;
    else                  Cp = C;

    int tid = threadIdx.x;
    int tx = tid % 16;          // col group (4 cols)
    int ty = tid / 16;          // row group (4 rows)
    int m0 = blockIdx.y * BM;
    int n0 = blockIdx.x * BN;

    int lr = tid / 4;           // 0..63 row within tile
    int lk = (tid % 4) * 4;     // k offset within BKT

    // acc2[ip][j]: packed pair of rows (ty*4 + 2*ip, ty*4 + 2*ip + 1), col tx*4+j
    u64 acc2[2][4];
    #pragma unroll
    for (int ip = 0; ip < 2; ip++)
        #pragma unroll
        for (int j = 0; j < 4; j++) acc2[ip][j] = 0ull;

    for (int k0 = 0; k0 < GK; k0 += BKT) {
        float4 av = *(const float4*)&Ap[(size_t)(m0 + lr) * GK + k0 + lk];
        float4 wv = *(const float4*)&W [(size_t)(n0 + lr) * GK + k0 + lk];
        As[lk+0][lr] = av.x; As[lk+1][lr] = av.y; As[lk+2][lr] = av.z; As[lk+3][lr] = av.w;
        Ws[lk+0][lr] = wv.x; Ws[lk+1][lr] = wv.y; Ws[lk+2][lr] = wv.z; Ws[lk+3][lr] = wv.w;
        __syncthreads();

        #pragma unroll
        for (int kk = 0; kk < BKT; kk++) {
            // one LDS.128 yields two packed row-pairs of A
            ulonglong2 a2 = *(const ulonglong2*)&As[kk][ty * 4];
            float4 w4 = *(const float4*)&Ws[kk][tx * 4];
            u64 w0 = pack2(w4.x, w4.x);
            u64 w1 = pack2(w4.y, w4.y);
            u64 w2 = pack2(w4.z, w4.z);
            u64 w3 = pack2(w4.w, w4.w);
            acc2[0][0] = ffma2(a2.x, w0, acc2[0][0]);
            acc2[0][1] = ffma2(a2.x, w1, acc2[0][1]);
            acc2[0][2] = ffma2(a2.x, w2, acc2[0][2]);
            acc2[0][3] = ffma2(a2.x, w3, acc2[0][3]);
            acc2[1][0] = ffma2(a2.y, w0, acc2[1][0]);
            acc2[1][1] = ffma2(a2.y, w1, acc2[1][1]);
            acc2[1][2] = ffma2(a2.y, w2, acc2[1][2]);
            acc2[1][3] = ffma2(a2.y, w3, acc2[1][3]);
        }
        __syncthreads();
    }

    #pragma unroll
    for (int ip = 0; ip < 2; ip++) {
        #pragma unroll
        for (int j = 0; j < 4; j++) {
            float vlo, vhi;
            unpack2(acc2[ip][j], vlo, vhi);
            int n = n0 + tx * 4 + j;
            float bval = bias[n];
            #pragma unroll
            for (int half = 0; half < 2; half++) {
                int m = m0 + ty * 4 + ip * 2 + half;
                float val = (half ? vhi : vlo) + bval;
                if (outsel < 3) {
                    int b = m / LL, l = m % LL;
                    int h = n / DD, d = n % DD;
                    Cp[(((size_t)(b * HH + h)) * LL + l) * DD + d] = val;
                } else {
                    Cp[(size_t)m * GN + n] = val;
                }
            }
        }
    }
}

// ---------------------------------------------------------------------------
// Fused flash attention with packed fp32x2 FMA.
// Per (b,h): 128 query rows per CTA (one per thread), K/V tiles of 64 rows in
// SMEM, online softmax in two 32-wide halves. Writes O as [B,L,E].
// ---------------------------------------------------------------------------
#define BQ 128
#define BKK 64
#define SCALE 0.04419417382415922f          // 1/sqrt(512)
#define MASKVAL (-4.4194173824159216e18f)   // -1e20 * SCALE

__global__ __launch_bounds__(128) void attn_kernel()
{
    __shared__ float Ks[BKK][DD];
    __shared__ float Vs[BKK][DD];

    int r  = threadIdx.x;                // one query row per thread
    int bh = blockIdx.y;
    int b  = bh / HH;
    int h  = bh % HH;
    int qi = blockIdx.x * BQ + r;

    // q as 32 packed pairs
    const u64* qptr = (const u64*)(g_q + ((size_t)bh * LL + qi) * DD);
    u64 q2[32];
    #pragma unroll
    for (int i = 0; i < 32; i++) q2[i] = qptr[i];

    u64 o2[32];
    #pragma unroll
    for (int i = 0; i < 32; i++) o2[i] = 0ull;   // bit pattern of (0.f, 0.f)

    float m = -1e30f, l = 0.f;

    const unsigned int* mrow = g_mb + ((size_t)b * LL + qi) * NWORDS;

    for (int k0 = 0; k0 < LL; k0 += BKK) {
        // cooperative K/V tile load (1024 float4 each, 128 threads -> 8 iters)
        const float4* kbase = (const float4*)(g_k + ((size_t)bh * LL + k0) * DD);
        const float4* vbase = (const float4*)(g_v + ((size_t)bh * LL + k0) * DD);
        float4* ksh = (float4*)Ks;
        float4* vsh = (float4*)Vs;
        #pragma unroll
        for (int i = 0; i < 8; i++) {
            ksh[r + i * 128] = kbase[r + i * 128];
            vsh[r + i * 128] = vbase[r + i * 128];
        }
        __syncthreads();

        unsigned int wb0 = mrow[(k0 >> 5) + 0];
        unsigned int wb1 = mrow[(k0 >> 5) + 1];

        #pragma unroll
        for (int half = 0; half < 2; half++) {
            unsigned int bits = half ? wb1 : wb0;
            float s[32];
            float tmax = -3.0e38f;
            #pragma unroll
            for (int kk = 0; kk < 32; kk++) {
                const ulonglong2* kr = (const ulonglong2*)&Ks[half * 32 + kk][0];
                u64 a0 = 0ull, a1 = 0ull, a2 = 0ull, a3 = 0ull;
                #pragma unroll
                for (int i = 0; i < 8; i++) {
                    ulonglong2 kv0 = kr[2 * i];
                    ulonglong2 kv1 = kr[2 * i + 1];
                    a0 = ffma2(q2[4 * i + 0], kv0.x, a0);
                    a1 = ffma2(q2[4 * i + 1], kv0.y, a1);
                    a2 = ffma2(q2[4 * i + 2], kv1.x, a2);
                    a3 = ffma2(q2[4 * i + 3], kv1.y, a3);
                }
                u64 ap = fadd2(fadd2(a0, a1), fadd2(a2, a3));
                float alo, ahi;
                unpack2(ap, alo, ahi);
                float acc = alo + ahi;
                float sv = ((bits >> kk) & 1u) ? acc * SCALE : MASKVAL;
                s[kk] = sv;
                tmax = fmaxf(tmax, sv);
            }
            float mnew = fmaxf(m, tmax);
            float corr = __expf(m - mnew);
            l *= corr;
            u64 corr2 = pack2(corr, corr);
            #pragma unroll
            for (int i = 0; i < 32; i++) o2[i] = fmul2(o2[i], corr2);
            #pragma unroll
            for (int kk = 0; kk < 32; kk++) {
                float p = __expf(s[kk] - mnew);
                l += p;
                u64 pp = pack2(p, p);
                const ulonglong2* vr = (const ulonglong2*)&Vs[half * 32 + kk][0];
                #pragma unroll
                for (int i = 0; i < 8; i++) {
                    ulonglong2 v0 = vr[2 * i];
                    ulonglong2 v1 = vr[2 * i + 1];
                    o2[4 * i + 0] = ffma2(pp, v0.x, o2[4 * i + 0]);
                    o2[4 * i + 1] = ffma2(pp, v0.y, o2[4 * i + 1]);
                    o2[4 * i + 2] = ffma2(pp, v1.x, o2[4 * i + 2]);
                    o2[4 * i + 3] = ffma2(pp, v1.y, o2[4 * i + 3]);
                }
            }
            m = mnew;
        }
        __syncthreads();
    }

    float inv = 1.f / l;
    u64 inv2 = pack2(inv, inv);
    ulonglong2* optr = (ulonglong2*)(g_o + ((size_t)(b * LL + qi)) * EE + h * DD);
    #pragma unroll
    for (int i = 0; i < 16; i++) {
        ulonglong2 ov;
        ov.x = fmul2(o2[2 * i + 0], inv2);
        ov.y = fmul2(o2[2 * i + 1], inv2);
        optr[i] = ov;
    }
}

// ---------------------------------------------------------------------------
// kernel_launch
// inputs: 0 values, 1 keys, 2 query, 3 mask, 4 Wv, 5 bv, 6 Wk, 7 bk,
//         8 Wq, 9 bq, 10 Wo, 11 bo
// ---------------------------------------------------------------------------
extern "C" void kernel_launch(void* const* d_in, const int* in_sizes, int n_in,
                              void* d_out, int out_size)
{
    const float* values = (const float*)d_in[0];
    const float* keys   = (const float*)d_in[1];
    const float* query  = (const float*)d_in[2];
    const int*   mask   = (const int*)d_in[3];
    const float* Wv = (const float*)d_in[4];
    const float* bv = (const float*)d_in[5];
    const float* Wk = (const float*)d_in[6];
    const float* bk = (const float*)d_in[7];
    const float* Wq = (const float*)d_in[8];
    const float* bq = (const float*)d_in[9];
    const float* Wo = (const float*)d_in[10];
    const float* bo = (const float*)d_in[11];
    float* out = (float*)d_out;

    // mask bit-pack (ballot, fully coalesced)
    pack_mask_kernel<<<(Bb * LL * LL) / 256, 256>>>(mask);

    // projections (head-split outputs)
    dim3 ggrid(GN / BN, GM / BM);   // (8, 64)
    gemm_bias_kernel<<<ggrid, 256>>>(values, Wv, bv, nullptr, 0);  // -> g_v
    gemm_bias_kernel<<<ggrid, 256>>>(keys,   Wk, bk, nullptr, 1);  // -> g_k
    gemm_bias_kernel<<<ggrid, 256>>>(query,  Wq, bq, nullptr, 2);  // -> g_q

    // fused attention -> g_o [B, L, E]
    attn_kernel<<<dim3(LL / BQ, Bb * HH), 128>>>();

    // output projection -> d_out
    gemm_bias_kernel<<<ggrid, 256>>>(nullptr, Wo, bo, out, 3);     // g_o @ Wo^T + bo
}

// round 6
// speedup vs baseline: 1.7356x; 1.0948x over previous
#include <cuda_runtime.h>
#include <math.h>

// Problem constants
#define Bb 2
#define LL 2048
#define EE 512
#define HH 8
#define DD 64
#define NWORDS (LL/32)

// Scratch (device globals -- no allocation allowed)
__device__ float g_q[Bb*HH*LL*DD];
__device__ float g_k[Bb*HH*LL*DD];
__device__ float g_v[Bb*HH*LL*DD];
__device__ float g_o[Bb*LL*EE];
__device__ unsigned int g_mb[Bb*LL*NWORDS];

// ---------------------------------------------------------------------------
// Packed fp32x2 helpers
// ---------------------------------------------------------------------------
typedef unsigned long long u64;

__device__ __forceinline__ u64 pack2(float lo, float hi) {
    u64 r; asm("mov.b64 %0, {%1, %2};" : "=l"(r) : "f"(lo), "f"(hi)); return r;
}
__device__ __forceinline__ void unpack2(u64 v, float &lo, float &hi) {
    asm("mov.b64 {%0, %1}, %2;" : "=f"(lo), "=f"(hi) : "l"(v));
}
__device__ __forceinline__ u64 ffma2(u64 a, u64 b, u64 c) {
    u64 d; asm("fma.rn.f32x2 %0, %1, %2, %3;" : "=l"(d) : "l"(a), "l"(b), "l"(c)); return d;
}
__device__ __forceinline__ u64 fadd2(u64 a, u64 b) {
    u64 d; asm("add.rn.f32x2 %0, %1, %2;" : "=l"(d) : "l"(a), "l"(b)); return d;
}
__device__ __forceinline__ u64 fmul2(u64 a, u64 b) {
    u64 d; asm("mul.rn.f32x2 %0, %1, %2;" : "=l"(d) : "l"(a), "l"(b)); return d;
}
__device__ __forceinline__ float ex2f(float x) {
    float y; asm("ex2.approx.f32 %0, %1;" : "=f"(y) : "f"(x)); return y;
}
__device__ __forceinline__ void cp16(unsigned int d, const float* s) {
    asm volatile("cp.async.cg.shared.global [%0], [%1], 16;" :: "r"(d), "l"(s));
}

// ---------------------------------------------------------------------------
// Pack mask [B,1,L,L] int32 -> bitmask words via warp ballot (coalesced)
// ---------------------------------------------------------------------------
__global__ void pack_mask_kernel(const int* __restrict__ mask) {
    int idx = blockIdx.x * blockDim.x + threadIdx.x;
    unsigned int bit = (mask[idx] != 0) ? 1u : 0u;
    unsigned int word = __ballot_sync(0xffffffffu, bit);
    if ((threadIdx.x & 31) == 0) g_mb[idx >> 5] = word;
}

// ---------------------------------------------------------------------------
// GEMM body: C[M,N] = A[M,K] @ W^T + bias, M=4096 N=512 K=512.
// 128x128 CTA tile, 8x8 microtile (rows packed in fp32x2 pairs), 256 threads.
// k-major smem with +4 pad; register-prefetch double buffering of LDG.
// ---------------------------------------------------------------------------
#define GM 4096
#define GN 512
#define GK 512
#define BMt 128
#define BNt 128
#define BKT 16
#define LDS_A 132   // BMt + 4 pad (keeps 16B alignment, breaks 4-way STS conflict)

__device__ __forceinline__ void gemm_body(
    const float* __restrict__ Ap, const float* __restrict__ W,
    const float* __restrict__ bias, float* __restrict__ Cp, bool headsplit)
{
    __shared__ float As[BKT][LDS_A];
    __shared__ float Ws[BKT][LDS_A];

    int tid = threadIdx.x;
    int tx = tid % 16;          // col group (8 cols)
    int ty = tid / 16;          // row group (8 rows)
    int m0 = blockIdx.y * BMt;
    int n0 = blockIdx.x * BNt;

    int lr = tid >> 1;          // 0..127 row within tile
    int lk = (tid & 1) * 8;     // k offset 0 or 8

    const float* aSrc = &Ap[(size_t)(m0 + lr) * GK + lk];
    const float* wSrc = &W [(size_t)(n0 + lr) * GK + lk];

    float4 ra0, ra1, rw0, rw1;
    ra0 = *(const float4*)(aSrc + 0);
    ra1 = *(const float4*)(aSrc + 4);
    rw0 = *(const float4*)(wSrc + 0);
    rw1 = *(const float4*)(wSrc + 4);

    u64 acc[4][8];
    #pragma unroll
    for (int i = 0; i < 4; i++)
        #pragma unroll
        for (int j = 0; j < 8; j++) acc[i][j] = 0ull;

    for (int k0 = 0; k0 < GK; k0 += BKT) {
        As[lk+0][lr] = ra0.x; As[lk+1][lr] = ra0.y; As[lk+2][lr] = ra0.z; As[lk+3][lr] = ra0.w;
        As[lk+4][lr] = ra1.x; As[lk+5][lr] = ra1.y; As[lk+6][lr] = ra1.z; As[lk+7][lr] = ra1.w;
        Ws[lk+0][lr] = rw0.x; Ws[lk+1][lr] = rw0.y; Ws[lk+2][lr] = rw0.z; Ws[lk+3][lr] = rw0.w;
        Ws[lk+4][lr] = rw1.x; Ws[lk+5][lr] = rw1.y; Ws[lk+6][lr] = rw1.z; Ws[lk+7][lr] = rw1.w;
        __syncthreads();

        if (k0 + BKT < GK) {
            ra0 = *(const float4*)(aSrc + k0 + BKT + 0);
            ra1 = *(const float4*)(aSrc + k0 + BKT + 4);
            rw0 = *(const float4*)(wSrc + k0 + BKT + 0);
            rw1 = *(const float4*)(wSrc + k0 + BKT + 4);
        }

        #pragma unroll
        for (int kk = 0; kk < BKT; kk++) {
            ulonglong2 aA = *(const ulonglong2*)&As[kk][ty * 8];
            ulonglong2 aB = *(const ulonglong2*)&As[kk][ty * 8 + 4];
            float4 wa = *(const float4*)&Ws[kk][tx * 8];
            float4 wb = *(const float4*)&Ws[kk][tx * 8 + 4];
            u64 a[4] = {aA.x, aA.y, aB.x, aB.y};
            u64 w[8];
            w[0] = pack2(wa.x, wa.x); w[1] = pack2(wa.y, wa.y);
            w[2] = pack2(wa.z, wa.z); w[3] = pack2(wa.w, wa.w);
            w[4] = pack2(wb.x, wb.x); w[5] = pack2(wb.y, wb.y);
            w[6] = pack2(wb.z, wb.z); w[7] = pack2(wb.w, wb.w);
            #pragma unroll
            for (int i = 0; i < 4; i++)
                #pragma unroll
                for (int j = 0; j < 8; j++)
                    acc[i][j] = ffma2(a[i], w[j], acc[i][j]);
        }
        __syncthreads();
    }

    // epilogue
    #pragma unroll
    for (int j = 0; j < 8; j++) {
        int n = n0 + tx * 8 + j;
        float bval = bias[n];
        int h = n / DD, d = n % DD;
        #pragma unroll
        for (int i = 0; i < 4; i++) {
            float vlo, vhi;
            unpack2(acc[i][j], vlo, vhi);
            int m = m0 + ty * 8 + 2 * i;
            if (headsplit) {
                int b = m / LL, l = m % LL;
                size_t base = (((size_t)(b * HH + h)) * LL + l) * DD + d;
                Cp[base]      = vlo + bval;
                Cp[base + DD] = vhi + bval;   // l+1 -> +DD in [B,H,L,D]
            } else {
                Cp[(size_t)m * GN + n]       = vlo + bval;
                Cp[(size_t)(m + 1) * GN + n] = vhi + bval;
            }
        }
    }
}

__global__ __launch_bounds__(256) void qkv_gemm_kernel(
    const float* __restrict__ values, const float* __restrict__ keysp,
    const float* __restrict__ query,
    const float* __restrict__ Wv, const float* __restrict__ bv,
    const float* __restrict__ Wk, const float* __restrict__ bk,
    const float* __restrict__ Wq, const float* __restrict__ bq)
{
    int z = blockIdx.z;
    const float* A    = (z == 0) ? values : (z == 1) ? keysp : query;
    const float* W    = (z == 0) ? Wv : (z == 1) ? Wk : Wq;
    const float* bias = (z == 0) ? bv : (z == 1) ? bk : bq;
    float* C          = (z == 0) ? g_v : (z == 1) ? g_k : g_q;
    gemm_body(A, W, bias, C, true);
}

__global__ __launch_bounds__(256) void out_gemm_kernel(
    const float* __restrict__ Wo, const float* __restrict__ bo, float* __restrict__ C)
{
    gemm_body(g_o, Wo, bo, C, false);
}

// ---------------------------------------------------------------------------
// Fused flash attention, fp32x2 FMA, cp.async double-buffered 32-key tiles.
// Logits pre-scaled into log2 domain (SCALE * log2e folded into q).
// ---------------------------------------------------------------------------
#define BQ 128
#define BKK 32
#define NT (LL/BKK)
#define SCALE2   (0.04419417382415922f * 1.4426950408889634f)  // log2e/sqrt(512)
#define MASKVAL2 (-1e20f * 0.04419417382415922f * 1.4426950408889634f)

__global__ __launch_bounds__(128) void attn_kernel()
{
    __shared__ float Ks[2][BKK][DD];
    __shared__ float Vs[2][BKK][DD];

    int r  = threadIdx.x;
    int bh = blockIdx.y;
    int b  = bh / HH;
    int h  = bh % HH;
    int qi = blockIdx.x * BQ + r;

    const u64* qptr = (const u64*)(g_q + ((size_t)bh * LL + qi) * DD);
    u64 sc2 = pack2(SCALE2, SCALE2);
    u64 q2[32];
    #pragma unroll
    for (int i = 0; i < 32; i++) q2[i] = fmul2(qptr[i], sc2);

    u64 o2[32];
    #pragma unroll
    for (int i = 0; i < 32; i++) o2[i] = 0ull;

    float m = -1e30f, l = 0.f;

    const unsigned int* mrow = g_mb + ((size_t)b * LL + qi) * NWORDS;
    const float* kbase = g_k + (size_t)bh * LL * DD;
    const float* vbase = g_v + (size_t)bh * LL * DD;

    unsigned int kd0 = (unsigned int)__cvta_generic_to_shared(&Ks[0][0][0]);
    unsigned int vd0 = (unsigned int)__cvta_generic_to_shared(&Vs[0][0][0]);

    // prefetch tile 0 -> buffer 0
    {
        const float* kg = kbase;
        const float* vg = vbase;
        #pragma unroll
        for (int i = 0; i < 4; i++) {
            int idx = r + i * 128;             // float4 index 0..511
            cp16(kd0 + idx * 16, kg + idx * 4);
            cp16(vd0 + idx * 16, vg + idx * 4);
        }
        asm volatile("cp.async.commit_group;");
    }

    for (int t = 0; t < NT; t++) {
        __syncthreads();   // everyone finished reading buffer (t+1)&1 (from iter t-1)
        if (t + 1 < NT) {
            int nb = (t + 1) & 1;
            unsigned int kd = kd0 + nb * (BKK * DD * 4);
            unsigned int vd = vd0 + nb * (BKK * DD * 4);
            const float* kg = kbase + (size_t)(t + 1) * BKK * DD;
            const float* vg = vbase + (size_t)(t + 1) * BKK * DD;
            #pragma unroll
            for (int i = 0; i < 4; i++) {
                int idx = r + i * 128;
                cp16(kd + idx * 16, kg + idx * 4);
                cp16(vd + idx * 16, vg + idx * 4);
            }
            asm volatile("cp.async.commit_group;");
            asm volatile("cp.async.wait_group 1;");
        } else {
            asm volatile("cp.async.wait_group 0;");
        }
        __syncthreads();   // tile t visible to all threads

        int cb = t & 1;
        unsigned int bits = mrow[t];

        float s[32];
        float tmax = -3.0e38f;
        #pragma unroll
        for (int kk = 0; kk < 32; kk++) {
            const ulonglong2* kr = (const ulonglong2*)&Ks[cb][kk][0];
            u64 a0 = 0ull, a1 = 0ull, a2 = 0ull, a3 = 0ull;
            #pragma unroll
            for (int i = 0; i < 8; i++) {
                ulonglong2 kv0 = kr[2 * i];
                ulonglong2 kv1 = kr[2 * i + 1];
                a0 = ffma2(q2[4 * i + 0], kv0.x, a0);
                a1 = ffma2(q2[4 * i + 1], kv0.y, a1);
                a2 = ffma2(q2[4 * i + 2], kv1.x, a2);
                a3 = ffma2(q2[4 * i + 3], kv1.y, a3);
            }
            u64 ap = fadd2(fadd2(a0, a1), fadd2(a2, a3));
            float alo, ahi;
            unpack2(ap, alo, ahi);
            float acc = alo + ahi;
            float sv = ((bits >> kk) & 1u) ? acc : MASKVAL2;
            s[kk] = sv;
            tmax = fmaxf(tmax, sv);
        }
        float mnew = fmaxf(m, tmax);
        if (mnew > m) {             // skip rescale when running max unchanged
            float corr = ex2f(m - mnew);
            l *= corr;
            u64 corr2 = pack2(corr, corr);
            #pragma unroll
            for (int i = 0; i < 32; i++) o2[i] = fmul2(o2[i], corr2);
        }
        #pragma unroll
        for (int kk = 0; kk < 32; kk++) {
            float p = ex2f(s[kk] - mnew);
            l += p;
            u64 pp = pack2(p, p);
            const ulonglong2* vr = (const ulonglong2*)&Vs[cb][kk][0];
            #pragma unroll
            for (int i = 0; i < 8; i++) {
                ulonglong2 v0 = vr[2 * i];
                ulonglong2 v1 = vr[2 * i + 1];
                o2[4 * i + 0] = ffma2(pp, v0.x, o2[4 * i + 0]);
                o2[4 * i + 1] = ffma2(pp, v0.y, o2[4 * i + 1]);
                o2[4 * i + 2] = ffma2(pp, v1.x, o2[4 * i + 2]);
                o2[4 * i + 3] = ffma2(pp, v1.y, o2[4 * i + 3]);
            }
        }
        m = mnew;
    }

    float inv = 1.f / l;
    u64 inv2 = pack2(inv, inv);
    ulonglong2* optr = (ulonglong2*)(g_o + ((size_t)(b * LL + qi)) * EE + h * DD);
    #pragma unroll
    for (int i = 0; i < 16; i++) {
        ulonglong2 ov;
        ov.x = fmul2(o2[2 * i + 0], inv2);
        ov.y = fmul2(o2[2 * i + 1], inv2);
        optr[i] = ov;
    }
}

// ---------------------------------------------------------------------------
// kernel_launch
// ---------------------------------------------------------------------------
extern "C" void kernel_launch(void* const* d_in, const int* in_sizes, int n_in,
                              void* d_out, int out_size)
{
    const float* values = (const float*)d_in[0];
    const float* keys   = (const float*)d_in[1];
    const float* query  = (const float*)d_in[2];
    const int*   mask   = (const int*)d_in[3];
    const float* Wv = (const float*)d_in[4];
    const float* bv = (const float*)d_in[5];
    const float* Wk = (const float*)d_in[6];
    const float* bk = (const float*)d_in[7];
    const float* Wq = (const float*)d_in[8];
    const float* bq = (const float*)d_in[9];
    const float* Wo = (const float*)d_in[10];
    const float* bo = (const float*)d_in[11];
    float* out = (float*)d_out;

    pack_mask_kernel<<<(Bb * LL * LL) / 256, 256>>>(mask);

    dim3 qkv_grid(GN / BNt, GM / BMt, 3);   // (4, 32, 3)
    qkv_gemm_kernel<<<qkv_grid, 256>>>(values, keys, query, Wv, bv, Wk, bk, Wq, bq);

    attn_kernel<<<dim3(LL / BQ, Bb * HH), 128>>>();

    dim3 o_grid(GN / BNt, GM / BMt);        // (4, 32)
    out_gemm_kernel<<<o_grid, 256>>>(Wo, bo, out);
}